// round 15
// baseline (speedup 1.0000x reference)
#include <cuda_runtime.h>

// Problem constants
#define TABN    512             // table intervals over [-16, 16], h = 2^-4
#define NSTEP   32
#define NPATH   65536
#define DTC     0.03125f
#define SIG_CF  0.2f
#define CDT     0.0015625f      // DT * MU_C
#define CDT2    (CDT * CDT)

#define TPB     128
#define NBLK    (NPATH / TPB)   // 512 blocks, all co-resident (see launch_bounds)
#define NBUILD  64              // builder blocks, 8 table entries each

// Scratch (static device globals; no runtime allocation)
__device__ float4   g_tab[TABN];       // (y_i, dy_i, tanh_i, dtanh_i)
__device__ float2   g_part[NBLK];      // per-block (sum ycv^2, sum yT^2)
__device__ unsigned g_ready = 0;       // builder completion count (winner resets)
__device__ unsigned g_ctr   = 0;       // last-block ticket       (winner resets)

// ---------------------------------------------------------------------------
// ONE fused kernel.
//  Blocks 0..63: build 8 (value, slope) table entries each (9 overlapping MLP
//  points -> no cross-block dependency), release via g_ready.
//  ALL blocks: stage dW tile (overlaps the build), spin for g_ready==64,
//  stage table to smem, pull per-thread dW into registers, run 32 pipelined
//  tamed-Euler steps, deterministic fused reduction; winner block writes the
//  loss and resets the counters for the next graph replay.
// Residency proof (no-deadlock): __launch_bounds__(128,4) caps regs so >=4
// blocks/SM; smem 43.7KB -> 5/SM; 4*148=592 >= 512 -> all blocks in wave 1.
// ---------------------------------------------------------------------------
__global__ __launch_bounds__(TPB, 4) void fused_kernel(
    const float* __restrict__ x0, const float* __restrict__ dW,
    const float* __restrict__ W1, const float* __restrict__ b1,
    const float* __restrict__ W2, const float* __restrict__ b2,
    const float* __restrict__ W3, const float* __restrict__ b3,
    float* __restrict__ out)
{
    __shared__ float4 stab[TABN];        // 8 KB   table
    __shared__ float  sdw[TPB * 36];     // 18 KB  dW tile, row stride 36 (16B-aligned rows)
    __shared__ float  sW2[64 * 64];      // 16 KB  (builders only)
    __shared__ float  sh1[128];
    __shared__ float  sred[4];
    __shared__ float  sY[9];

    const int tid = threadIdx.x;
    const int bb  = blockIdx.x;

    // ================= build phase (blocks 0..NBUILD-1) =================
    if (bb < NBUILD) {
        {   // stage W2 (coalesced float4)
            const float4* src = (const float4*)W2;
            float4* dst = (float4*)sW2;
            #pragma unroll
            for (int k = 0; k < 8; k++) dst[tid + TPB * k] = src[tid + TPB * k];
        }
        const int p = tid >> 6, j = tid & 63;      // 2 point-groups x 64 neurons
        const float w1x = W1[64 + j], b1j = b1[j], b2j = b2[j], w3j = W3[2 * j];
        __syncthreads();

        // 9 overlapping points (0..8) in 5 rounds of 2
        for (int g = 0; g < 5; g++) {
            const int l  = g * 2 + p;              // 0..9
            const int lv = l > 8 ? 8 : l;
            const float xg = -16.0f + (float)(bb * 8 + lv) * 0.0625f;
            sh1[p * 64 + j] = tanhf(fmaf(xg, w1x, b1j));
            __syncthreads();
            float a = b2j;
            #pragma unroll
            for (int k = 0; k < 64; k++)
                a = fmaf(sh1[p * 64 + k], sW2[k * 64 + j], a);
            float c = tanhf(a) * w3j;
            #pragma unroll
            for (int off = 16; off > 0; off >>= 1)
                c += __shfl_xor_sync(0xFFFFFFFFu, c, off);
            if ((tid & 31) == 0) sred[tid >> 5] = c;
            __syncthreads();
            if (tid < 2 && g * 2 + tid <= 8)
                sY[g * 2 + tid] = sred[2 * tid] + sred[2 * tid + 1] + b3[0];
            __syncthreads();
        }
        if (tid < 8) {
            const int i = bb * 8 + tid;
            const float xi = -16.0f + (float)i * 0.0625f;
            const float t0 = tanhf(xi), t1 = tanhf(xi + 0.0625f);
            g_tab[i] = make_float4(sY[tid], sY[tid + 1] - sY[tid], t0, t1 - t0);
        }
        __syncthreads();
        if (tid == 0) { __threadfence(); atomicAdd(&g_ready, 1u); }   // release
    }

    // ================= path phase (ALL blocks) =================
    // Stage dW tile (128 paths x 32 steps = 1024 float4) -- overlaps the build
    {
        const float4* g = (const float4*)dW + (size_t)bb * (TPB * 8);
        #pragma unroll
        for (int k = 0; k < 8; k++) {
            const int c = tid + TPB * k;           // consecutive across lanes
            const float4 v = __ldg(&g[c]);
            ((float4*)(sdw + (c >> 3) * 36))[c & 7] = v;   // STS.128, aligned
        }
    }
    float x = __ldg(&x0[bb * TPB + tid]);

    // Wait for the table
    if (tid == 0) {
        while (*((volatile unsigned*)&g_ready) < NBUILD) __nanosleep(64);
    }
    __syncthreads();
    __threadfence();                               // acquire

    // Stage table via L2 (.cg: never trust L1 for cross-SM-produced data)
    #pragma unroll
    for (int k = 0; k < 4; k++) {
        const int c = tid + TPB * k;
        stab[c] = __ldcg(&g_tab[c]);
    }
    __syncthreads();

    // Pull my dW row into registers (8 aligned LDS.128, one-time)
    float dwr[NSTEP];
    {
        const float4* row = (const float4*)(sdw + tid * 36);
        #pragma unroll
        for (int k = 0; k < 8; k++) {
            const float4 v = row[k];
            dwr[4 * k + 0] = v.x; dwr[4 * k + 1] = v.y;
            dwr[4 * k + 2] = v.z; dwr[4 * k + 3] = v.w;
        }
    }

    // 32 pipelined steps: next step's LDS is issued off the x-chain before the
    // current entry is consumed, hiding the 29-cyc LDS latency.
    float ylin = 1.0f, acc = 0.0f;

    float u  = fmaf(x, 16.0f, 256.0f);             // u = (x+16)*16 in (0,512)
    float uf = u + 8388607.5f;                     // 2^23 - 0.5 magic
    int   ti = __float_as_int(uf) & (TABN - 1);
    float f  = u - (uf - 8388608.0f);
    float4 e = stab[ti];

    #pragma unroll
    for (int s = 0; s < NSTEP; s++) {
        // advance x (independent of the pending table entry)
        const float a  = fmaf(SIG_CF, dwr[s], 1.0f + CDT);
        const float xn = x * (a - CDT2 * fabsf(x));
        // prefetch next entry
        const float un  = fmaf(xn, 16.0f, 256.0f);
        const float ufn = un + 8388607.5f;
        const int   tin = __float_as_int(ufn) & (TABN - 1);
        const float fn  = un - (ufn - 8388608.0f);
        const float4 en = stab[tin];
        // consume current entry (uses pre-update x)
        const float y   = fmaf(f, e.y, e.x);       // y(x)
        const float th  = fmaf(f, e.w, e.z);       // tanh(x)
        const float ycv = y - ylin;
        acc  = fmaf(ycv, ycv, acc);
        ylin = fmaf(-DTC, th, ylin);
        x = xn; e = en; f = fn;
    }

    float yT2 = ylin * ylin;

    // Deterministic block reduction (4 warps)
    #pragma unroll
    for (int off = 16; off > 0; off >>= 1) {
        acc += __shfl_xor_sync(0xFFFFFFFFu, acc, off);
        yT2 += __shfl_xor_sync(0xFFFFFFFFu, yT2, off);
    }
    __shared__ float2 sp[TPB / 32];
    __shared__ bool   s_last;
    if ((tid & 31) == 0) sp[tid >> 5] = make_float2(acc, yT2);
    __syncthreads();
    if (tid == 0) {
        float s1 = 0.0f, s2 = 0.0f;
        #pragma unroll
        for (int w = 0; w < TPB / 32; w++) { s1 += sp[w].x; s2 += sp[w].y; }
        g_part[bb] = make_float2(s1, s2);
        __threadfence();
        const unsigned t = atomicAdd(&g_ctr, 1u);
        s_last = (t == NBLK - 1);
    }
    __syncthreads();

    // Winner block: deterministic fixed-order final reduction + counter reset
    if (s_last) {
        __threadfence();
        double a1 = 0.0, a2 = 0.0;
        #pragma unroll
        for (int k = tid; k < NBLK; k += TPB) {
            const float2 pp = g_part[k];
            a1 += (double)pp.x;
            a2 += (double)pp.y;
        }
        #pragma unroll
        for (int off = 16; off > 0; off >>= 1) {
            a1 += __shfl_xor_sync(0xFFFFFFFFu, a1, off);
            a2 += __shfl_xor_sync(0xFFFFFFFFu, a2, off);
        }
        __shared__ double sd[8];
        if ((tid & 31) == 0) {
            sd[tid >> 5]       = a1;
            sd[4 + (tid >> 5)] = a2;
        }
        __syncthreads();
        if (tid == 0) {
            const double s1 = sd[0] + sd[1] + sd[2] + sd[3];
            const double s2 = sd[4] + sd[5] + sd[6] + sd[7];
            const double loss = s1 / (double)((long long)NSTEP * NPATH)
                              + 0.01 * (s2 / (double)NPATH);
            out[0]  = (float)loss;
            g_ready = 0;                           // reset for next replay
            g_ctr   = 0;
        }
    }
}

// ---------------------------------------------------------------------------
// Single launch. Inputs (metadata order): x0, dW, W1, b1, W2, b2, W3, b3
// ---------------------------------------------------------------------------
extern "C" void kernel_launch(void* const* d_in, const int* in_sizes, int n_in,
                              void* d_out, int out_size)
{
    const float* x0 = (const float*)d_in[0];
    const float* dW = (const float*)d_in[1];
    const float* W1 = (const float*)d_in[2];
    const float* b1 = (const float*)d_in[3];
    const float* W2 = (const float*)d_in[4];
    const float* b2 = (const float*)d_in[5];
    const float* W3 = (const float*)d_in[6];
    const float* b3 = (const float*)d_in[7];
    (void)in_sizes; (void)n_in; (void)out_size;

    fused_kernel<<<NBLK, TPB>>>(x0, dW, W1, b1, W2, b2, W3, b3, (float*)d_out);
}

// round 16
// speedup vs baseline: 1.0388x; 1.0388x over previous
#include <cuda_runtime.h>
#include <cstdint>

// Problem constants
#define TABN    512             // table intervals over [-16, 16], h = 2^-4
#define NSTEP   32
#define NPATH   65536
#define DTC     0.03125f
#define SIG_CF  0.2f
#define CDT     0.0015625f      // DT * MU_C
#define CDT2    (CDT * CDT)

#define TPB     128
#define NBLK    (NPATH / TPB)   // 512
#define BK_TPB  576             // 9 points x 64 neurons
#define NBUILD  (TABN / 8)      // 64 builder blocks x 8 intervals

// Scratch (static device globals; no runtime allocation)
__device__ float4   g_tab[TABN];       // (y_i, dy_i, tanh_i, dtanh_i)
__device__ float2   g_part[NBLK];      // per-block (sum ycv^2, sum yT^2)
__device__ unsigned g_ready = 0;       // build-release flag (winner resets)
__device__ unsigned g_ctr   = 0;       // last-block ticket   (winner resets)

__device__ __forceinline__ void cp_async16(void* dst_smem, const void* src_gmem) {
    const uint32_t d = (uint32_t)__cvta_generic_to_shared(dst_smem);
    asm volatile("cp.async.cg.shared.global [%0], [%1], 16;\n" :: "r"(d), "l"(src_gmem));
}

// ---------------------------------------------------------------------------
// Build kernel (64 blocks): 9 overlapping MLP points -> 8 complete
// (value, slope) table entries per block. Releases path kernel via g_ready.
// Runs CONCURRENTLY with the path kernel's dW staging (parallel graph nodes).
// ---------------------------------------------------------------------------
__global__ __launch_bounds__(BK_TPB) void build_kernel(
    const float* __restrict__ W1, const float* __restrict__ b1,
    const float* __restrict__ W2, const float* __restrict__ b2,
    const float* __restrict__ W3, const float* __restrict__ b3)
{
    __shared__ float sW2[64 * 64];   // 16 KB
    __shared__ float sh1[9 * 64];
    __shared__ float sred[18];
    __shared__ float sY[9];

    const int tid = threadIdx.x;

    // Stage W2 into shared memory (coalesced float4)
    {
        const float4* src = (const float4*)W2;
        float4* dst = (float4*)sW2;
        for (int i = tid; i < 1024; i += BK_TPB) dst[i] = src[i];
    }

    const int p  = tid >> 6;                 // local point 0..8
    const int j  = tid & 63;                 // output neuron 0..63
    const int pt = blockIdx.x * 8 + p;       // global table point
    const float h = 32.0f / (float)TABN;
    const float x = -16.0f + (float)pt * h;

    sh1[tid] = tanhf(fmaf(x, W1[64 + j], b1[j]));
    __syncthreads();

    float a = b2[j];
    #pragma unroll
    for (int k = 0; k < 64; k++)
        a = fmaf(sh1[p * 64 + k], sW2[k * 64 + j], a);

    float contrib = tanhf(a) * W3[2 * j];

    #pragma unroll
    for (int off = 16; off > 0; off >>= 1)
        contrib += __shfl_xor_sync(0xFFFFFFFFu, contrib, off);
    if ((tid & 31) == 0) sred[tid >> 5] = contrib;
    __syncthreads();

    if (tid < 9) sY[tid] = sred[2 * tid] + sred[2 * tid + 1] + b3[0];
    __syncthreads();

    if (tid < 8) {
        const int i = blockIdx.x * 8 + tid;
        const float xi = -16.0f + (float)i * h;
        const float t0 = tanhf(xi), t1 = tanhf(xi + h);
        g_tab[i] = make_float4(sY[tid], sY[tid + 1] - sY[tid], t0, t1 - t0);
    }
    __syncthreads();
    if (tid == 0) { __threadfence(); atomicAdd(&g_ready, 1u); }   // release
}

// ---------------------------------------------------------------------------
// Path kernel (512 blocks): cp.async-stages its dW tile FIRST (8x16B per
// thread in flight -> full MLP on the 8MB DRAM stream), spins for the table,
// then runs 32 pipelined tamed-Euler steps per path + fused deterministic
// reduction. Winner block writes the loss and resets the flags for replay.
// Residency: 512 path (3.5/SM, <=8/SM cap) + 64 build blocks < 1 wave.
// ---------------------------------------------------------------------------
__global__ __launch_bounds__(TPB) void path_kernel(
    const float* __restrict__ x0, const float* __restrict__ dW,
    float* __restrict__ out)
{
    __shared__ float4 stab[TABN];        // 8 KB table
    __shared__ float  sdw[TPB * 36];     // 18 KB dW tile, row stride 36
    const int tid = threadIdx.x;
    const int bb  = blockIdx.x;

    // 1) Fire all dW staging copies (no register dependency -> MLP = 8)
    {
        const float4* g = (const float4*)dW + (size_t)bb * (TPB * 8);
        #pragma unroll
        for (int k = 0; k < 8; k++) {
            const int c = tid + TPB * k;                       // coalesced
            cp_async16(&((float4*)(sdw + (c >> 3) * 36))[c & 7], g + c);
        }
        asm volatile("cp.async.commit_group;\n" ::: "memory");
    }
    float x = __ldg(&x0[bb * TPB + tid]);

    // 2) Wait for the table (build runs concurrently with the copies above)
    if (tid == 0) {
        while (*((volatile unsigned*)&g_ready) < NBUILD) __nanosleep(32);
        __threadfence();                                       // acquire
    }
    __syncthreads();

    // 3) Stage table via L2 (.cg: produced by other SMs)
    #pragma unroll
    for (int k = 0; k < TABN / TPB; k++) {
        const int c = tid + TPB * k;
        stab[c] = __ldcg(&g_tab[c]);
    }
    asm volatile("cp.async.wait_group 0;\n" ::: "memory");
    __syncthreads();

    // 4) Pull my dW row into registers (8 aligned, phase-conflict-free LDS.128)
    float dwr[NSTEP];
    {
        const float4* row = (const float4*)(sdw + tid * 36);
        #pragma unroll
        for (int k = 0; k < 8; k++) {
            const float4 v = row[k];
            dwr[4 * k + 0] = v.x; dwr[4 * k + 1] = v.y;
            dwr[4 * k + 2] = v.z; dwr[4 * k + 3] = v.w;
        }
    }

    // 5) 32 pipelined steps (next LDS issued off the 12-cyc x-chain)
    float ylin = 1.0f, acc = 0.0f;

    float u  = fmaf(x, 16.0f, 256.0f);          // u = (x+16)*16 in (0,512)
    float uf = u + 8388607.5f;                  // 2^23 - 0.5 magic
    int   ti = __float_as_int(uf) & (TABN - 1);
    float f  = u - (uf - 8388608.0f);
    float4 e = stab[ti];

    #pragma unroll
    for (int s = 0; s < NSTEP; s++) {
        const float a  = fmaf(SIG_CF, dwr[s], 1.0f + CDT);
        const float xn = x * (a - CDT2 * fabsf(x));
        const float un  = fmaf(xn, 16.0f, 256.0f);           // prefetch next
        const float ufn = un + 8388607.5f;
        const int   tin = __float_as_int(ufn) & (TABN - 1);
        const float fn  = un - (ufn - 8388608.0f);
        const float4 en = stab[tin];
        const float y   = fmaf(f, e.y, e.x);                 // consume current
        const float th  = fmaf(f, e.w, e.z);
        const float ycv = y - ylin;
        acc  = fmaf(ycv, ycv, acc);
        ylin = fmaf(-DTC, th, ylin);
        x = xn; e = en; f = fn;
    }

    float yT2 = ylin * ylin;

    // Deterministic block reduction (4 warps)
    #pragma unroll
    for (int off = 16; off > 0; off >>= 1) {
        acc += __shfl_xor_sync(0xFFFFFFFFu, acc, off);
        yT2 += __shfl_xor_sync(0xFFFFFFFFu, yT2, off);
    }
    __shared__ float2 sp[TPB / 32];
    __shared__ bool   s_last;
    if ((tid & 31) == 0) sp[tid >> 5] = make_float2(acc, yT2);
    __syncthreads();
    if (tid == 0) {
        float s1 = 0.0f, s2 = 0.0f;
        #pragma unroll
        for (int w = 0; w < TPB / 32; w++) { s1 += sp[w].x; s2 += sp[w].y; }
        g_part[bb] = make_float2(s1, s2);
        __threadfence();
        const unsigned t = atomicAdd(&g_ctr, 1u);
        s_last = (t == NBLK - 1);
    }
    __syncthreads();

    // Winner block: deterministic fixed-order final reduction + flag reset
    if (s_last) {
        __threadfence();
        double a1 = 0.0, a2 = 0.0;
        #pragma unroll
        for (int k = tid; k < NBLK; k += TPB) {
            const float2 pp = g_part[k];
            a1 += (double)pp.x;
            a2 += (double)pp.y;
        }
        #pragma unroll
        for (int off = 16; off > 0; off >>= 1) {
            a1 += __shfl_xor_sync(0xFFFFFFFFu, a1, off);
            a2 += __shfl_xor_sync(0xFFFFFFFFu, a2, off);
        }
        __shared__ double sd[8];
        if ((tid & 31) == 0) {
            sd[tid >> 5]       = a1;
            sd[4 + (tid >> 5)] = a2;
        }
        __syncthreads();
        if (tid == 0) {
            const double s1 = sd[0] + sd[1] + sd[2] + sd[3];
            const double s2 = sd[4] + sd[5] + sd[6] + sd[7];
            const double loss = s1 / (double)((long long)NSTEP * NPATH)
                              + 0.01 * (s2 / (double)NPATH);
            out[0]  = (float)loss;
            g_ready = 0;                         // reset for next replay
            g_ctr   = 0;
        }
    }
}

// ---------------------------------------------------------------------------
// Launch: build and path as PARALLEL graph nodes (event fork/join so capture
// records them as independent; the device-side flag carries the real
// dependency). Streams/events are created fresh per call (kernel_launch is
// invoked only a handful of times; no device memory involved).
// Inputs (metadata order): x0, dW, W1, b1, W2, b2, W3, b3
// ---------------------------------------------------------------------------
extern "C" void kernel_launch(void* const* d_in, const int* in_sizes, int n_in,
                              void* d_out, int out_size)
{
    const float* x0 = (const float*)d_in[0];
    const float* dW = (const float*)d_in[1];
    const float* W1 = (const float*)d_in[2];
    const float* b1 = (const float*)d_in[3];
    const float* W2 = (const float*)d_in[4];
    const float* b2 = (const float*)d_in[5];
    const float* W3 = (const float*)d_in[6];
    const float* b3 = (const float*)d_in[7];
    (void)in_sizes; (void)n_in; (void)out_size;

    cudaStream_t s2;
    cudaEvent_t evA, evB;
    cudaStreamCreateWithFlags(&s2, cudaStreamNonBlocking);
    cudaEventCreateWithFlags(&evA, cudaEventDisableTiming);
    cudaEventCreateWithFlags(&evB, cudaEventDisableTiming);

    // Fork: path kernel on s2 runs concurrently with build on the main stream
    cudaEventRecord(evA, 0);
    cudaStreamWaitEvent(s2, evA, 0);

    build_kernel<<<NBUILD, BK_TPB>>>(W1, b1, W2, b2, W3, b3);
    path_kernel<<<NBLK, TPB, 0, s2>>>(x0, dW, (float*)d_out);

    // Join back onto the main stream
    cudaEventRecord(evB, s2);
    cudaStreamWaitEvent(0, evB, 0);
}